// round 12
// baseline (speedup 1.0000x reference)
#include <cuda_runtime.h>
#include <cstdint>

#define NB    32
#define CIN   256
#define HH    56
#define WW    56
#define KOUT  256
#define NPIX  (HH*WW)        // 3136
#define KDIM  (CIN*9)        // 2304
#define NCHUNK 72            // 2304 / 32 k-chunks
#define NTILES 896           // 14 r-tiles(4 rows) x 2 k-groups x 32 images

#define MTILE 128
#define NTILE 224            // 4 rows x 56

// stage layout (bytes), 128B k-rows of tf32: A 128x128B, B 224x128B
#define A_OFF  0
#define B_OFF  16384
#define STAGE  45056
#define SM_DYN (3*STAGE + 128)   // 135296 -> 1 CTA/SM

// ---------------- device scratch -------------------------------------------
__device__ __align__(16) float g_wt[KOUT * KDIM];
__device__ __align__(16) float g_xt[(size_t)NB * NPIX * CIN];
__device__ unsigned int g_tile_ctr;

// ---------------- PTX helpers ----------------------------------------------
__device__ __forceinline__ uint32_t smem_u32(const void* p) {
    uint32_t a;
    asm("{ .reg .u64 t; cvta.to.shared.u64 t, %1; cvt.u32.u64 %0, t; }"
        : "=r"(a) : "l"(p));
    return a;
}
__device__ __forceinline__ float to_tf32(float v) {
    uint32_t r;
    asm("cvt.rna.tf32.f32 %0, %1;" : "=r"(r) : "f"(v));
    return __uint_as_float(r);
}

#define CP16(dst, src, sz) \
    asm volatile("cp.async.cg.shared.global [%0], [%1], 16, %2;" \
                 :: "r"(dst), "l"(src), "r"(sz) : "memory")
#define CP_COMMIT() asm volatile("cp.async.commit_group;" ::: "memory")
#define CP_WAIT1()  asm volatile("cp.async.wait_group 1;" ::: "memory")

#define LDSM4(r, a) \
    asm volatile("ldmatrix.sync.aligned.m8n8.x4.shared.b16 {%0,%1,%2,%3}, [%4];" \
                 : "=r"((r)[0]),"=r"((r)[1]),"=r"((r)[2]),"=r"((r)[3]) : "r"(a))

#define MMAT(d, a, b) \
    asm volatile("mma.sync.aligned.m16n8k8.row.col.f32.tf32.tf32.f32 " \
                 "{%0,%1,%2,%3}, {%4,%5,%6,%7}, {%8,%9}, {%0,%1,%2,%3};" \
                 : "+f"((d)[0]),"+f"((d)[1]),"+f"((d)[2]),"+f"((d)[3]) \
                 : "r"((a)[0]),"r"((a)[1]),"r"((a)[2]),"r"((a)[3]), \
                   "r"((b)[0]),"r"((b)[1]))

// ---------------- fused prepass ---------------------------------------------
__global__ void prepass_all(const float* __restrict__ x,
                            const float* __restrict__ w) {
    __shared__ float t[32][33];
    const int tx = threadIdx.x, ty = threadIdx.y;   // 32 x 8

    if (blockIdx.z < NB) {
        const int n  = blockIdx.z;
        const int p0 = blockIdx.x * 32;
        const int c0 = blockIdx.y * 32;

        const float* xb = x + ((size_t)n * CIN + c0) * NPIX + p0;
        #pragma unroll
        for (int yy = ty; yy < 32; yy += 8)
            t[yy][tx] = xb[(size_t)yy * NPIX + tx];
        __syncthreads();

        size_t ob = ((size_t)n * NPIX + p0) * CIN + c0;
        #pragma unroll
        for (int yy = ty; yy < 32; yy += 8)
            g_xt[ob + (size_t)yy * CIN + tx] = to_tf32(t[tx][yy]);
    } else {
        const int b = blockIdx.y * gridDim.x + blockIdx.x;   // 0..783
        const int tl = ty * 32 + tx;
        if (b == 0 && tl == 0) g_tile_ctr = 0u;   // reset work queue each launch
        for (int i = b * 256 + tl; i < KOUT * KDIM; i += 784 * 256) {
            int k = i / KDIM, r = i % KDIM;
            int c = r / 9, tap = r % 9;
            g_wt[k * KDIM + tap * CIN + c] = to_tf32(w[i]);
        }
    }
}

// ---------------- main kernel: persistent, 1 CTA/SM, 256 regs ---------------
__global__ __launch_bounds__(256, 1)
void conv_mma_kernel(const float* __restrict__ bias, float* __restrict__ out)
{
    extern __shared__ __align__(16) char dsm_raw[];
    __shared__ unsigned s_tile;

    const int tid = threadIdx.x;
    const int wid = tid >> 5;
    const int L   = tid & 31;
    const int wm  = wid & 3;             // M group (out-ch quarter)
    const int wn  = wid >> 2;            // N half (pixels wn*112 .. +111)

    uint32_t raw = smem_u32(dsm_raw);
    uint32_t sm  = (raw + 127u) & ~127u;
    uint32_t bufs[3] = { sm, sm + STAGE, sm + 2 * STAGE };

    // ---- per-lane ldmatrix constants ----
    const int arowL = ((L >> 3) & 1) * 8 + (L & 7);
    const int akg   = L >> 4;
    const int bprowL = wn * 112 + ((L >> 4) & 1) * 8 + (L & 7);
    const int bpkg   = (L >> 3) & 1;

    // ---- staging coords + state ----
    int sr0 = 0, sk0 = 0, sn = 0;
    uint32_t giB[7], giA[4], szmask;

    auto decode = [&](int t) {
        sn = t / 28;
        const int rem = t - sn * 28;
        sk0 = (rem & 1) << 7;
        sr0 = (rem >> 1) << 2;           // 4-row tiles
    };
    auto setup_tap = [&](int tap) {
        const int kh = tap / 3 - 1, kw = tap % 3 - 1;
        uint32_t m = 0;
        #pragma unroll
        for (int s = 0; s < 7; ++s) {    // B: 224 rows x 8 vec16 = 1792 slots
            const int i = tid + s * 256;
            const int p = i >> 3, v = i & 7;
            const int r = sr0 + p / 56 + kh;
            const int w = p % 56 + kw;
            const bool in = ((unsigned)r < HH) & ((unsigned)w < WW);
            giB[s] = in ? (uint32_t)((sn * NPIX + r * WW + w) * CIN + v * 4) : 0u;
            if (in) m |= (1u << s);
        }
        #pragma unroll
        for (int s = 0; s < 4; ++s) {    // A: 128 rows x 8 vec16 = 1024 slots
            const int i = tid + s * 256;
            const int p = i >> 3, v = i & 7;
            giA[s] = (uint32_t)((sk0 + p) * KDIM + tap * CIN + v * 4);
        }
        szmask = m;
    };
    auto slot_off = [&](int s) -> uint32_t {
        const int i = tid + s * 256;
        const int p = i >> 3, v = i & 7;
        uint32_t bo = (uint32_t)(p << 7) + (v << 4);
        return bo ^ ((bo >> 3) & 0x70);
    };
    auto emitB = [&](uint32_t sb, int s) {
        const uint32_t sz = ((szmask >> s) & 1u) * 16u;
        CP16(sb + B_OFF + slot_off(s), g_xt + giB[s], sz);
    };
    auto emitA = [&](uint32_t sb, int s) {
        CP16(sb + A_OFF + slot_off(s), g_wt + giA[s], 16u);
    };
    auto advance = [&]() {
        #pragma unroll
        for (int s = 0; s < 7; ++s) giB[s] += 32;
        #pragma unroll
        for (int s = 0; s < 4; ++s) giA[s] += 32;
    };
    auto emit_all = [&](uint32_t sb) {
        #pragma unroll
        for (int s = 0; s < 7; ++s) emitB(sb, s);
        #pragma unroll
        for (int s = 0; s < 4; ++s) emitA(sb, s);
    };

    float acc[2][14][4];
    #pragma unroll
    for (int mi = 0; mi < 2; ++mi)
        #pragma unroll
        for (int ni = 0; ni < 14; ++ni)
            #pragma unroll
            for (int q = 0; q < 4; ++q)
                acc[mi][ni][q] = 0.0f;

    // ---- acquire first tile, stage its chunks 0,1 ----
    if (tid == 0) s_tile = atomicAdd(&g_tile_ctr, 1u);
    __syncthreads();
    if ((int)s_tile >= NTILES) return;
    decode((int)s_tile);
    setup_tap(0);
    emit_all(bufs[0]); CP_COMMIT(); advance();
    emit_all(bufs[1]); CP_COMMIT(); advance();

    int r0 = sr0, k0 = sk0, n = sn;
    bool vS = true;
    int rd = 0, wr = 2, lc = 0;

    // fragment loaders (ping-pong sets)
    auto loadF = [&](uint32_t (&bt)[14][2], uint32_t (&at)[2][4],
                     uint32_t sA, uint32_t sB, int ks) {
        #pragma unroll
        for (int pi = 0; pi < 7; ++pi) {
            const int row = bprowL + pi * 16;
            const int c16 = (ks * 2 + bpkg) ^ (row & 7);
            LDSM4(&bt[pi * 2][0], sB + (uint32_t)(row << 7) + (c16 << 4));
        }
        #pragma unroll
        for (int mi = 0; mi < 2; ++mi) {
            const int row = wm * 32 + mi * 16 + arowL;
            const int c16 = (ks * 2 + akg) ^ (row & 7);
            LDSM4(at[mi], sA + (uint32_t)(row << 7) + (c16 << 4));
        }
    };
    auto doMMA = [&](uint32_t (&bt)[14][2], uint32_t (&at)[2][4]) {
        #pragma unroll
        for (int mi = 0; mi < 2; ++mi)
            #pragma unroll
            for (int ni = 0; ni < 14; ++ni)
                MMAT(acc[mi][ni], at[mi], bt[ni]);
    };

    // ---- persistent main loop ----
    while (true) {
        CP_WAIT1();
        __syncthreads();

        if (lc == 69 && tid == 0) s_tile = atomicAdd(&g_tile_ctr, 1u);
        if (lc == 70) {
            const int tn = (int)s_tile;
            vS = (tn < NTILES);
            if (vS) { decode(tn); setup_tap(0); }
        }
        bool doStage = true;
        if (lc < 70) {
            const int ce = lc + 2;
            if ((ce & 7) == 0) setup_tap(ce >> 3);
        } else if (!vS) {
            doStage = false;
        }

        const uint32_t sb = bufs[rd], wb = bufs[wr];
        const uint32_t sA = sb + A_OFF, sB = sb + B_OFF;

        uint32_t bt0[14][2], at0[2][4], bt1[14][2], at1[2][4];

        // software-pipelined 4 k8-steps with staged cp.async interleave
        loadF(bt0, at0, sA, sB, 0);
        if (doStage) { emitB(wb, 0); emitB(wb, 1); emitB(wb, 2); }
        loadF(bt1, at1, sA, sB, 1);
        doMMA(bt0, at0);
        if (doStage) { emitB(wb, 3); emitB(wb, 4); emitB(wb, 5); }
        loadF(bt0, at0, sA, sB, 2);
        doMMA(bt1, at1);
        if (doStage) { emitB(wb, 6); emitA(wb, 0); emitA(wb, 1); }
        loadF(bt1, at1, sA, sB, 3);
        doMMA(bt0, at0);
        if (doStage) { emitA(wb, 2); emitA(wb, 3); }
        CP_COMMIT();                      // always: keep group accounting aligned
        if (doStage) advance();
        doMMA(bt1, at1);

        rd = (rd == 2) ? 0 : rd + 1;
        wr = (wr == 2) ? 0 : wr + 1;

        if (lc == 71) {
            // ---- epilogue (hides next tile's refill) ----
            const int gID = L >> 2;
            const int tig = L & 3;
            #pragma unroll
            for (int mi = 0; mi < 2; ++mi) {
                const int kbase = k0 + wm * 32 + mi * 16 + gID;
                const float b0 = bias[kbase];
                const float b1 = bias[kbase + 8];
                #pragma unroll
                for (int rr = 0; rr < 2; ++rr) {
                    const int r = r0 + wn * 2 + rr;
                    float* o0 = out + (((size_t)n * KOUT + kbase)     * HH + r) * WW;
                    float* o1 = out + (((size_t)n * KOUT + kbase + 8) * HH + r) * WW;
                    #pragma unroll
                    for (int nj = 0; nj < 7; ++nj) {
                        const int ni = rr * 7 + nj;
                        const int c = nj * 8 + tig * 2;
                        float2 v0 = make_float2(acc[mi][ni][0] + b0, acc[mi][ni][1] + b0);
                        float2 v1 = make_float2(acc[mi][ni][2] + b1, acc[mi][ni][3] + b1);
                        *reinterpret_cast<float2*>(o0 + c) = v0;
                        *reinterpret_cast<float2*>(o1 + c) = v1;
                    }
                }
            }
            if (!vS) break;
            #pragma unroll
            for (int mi = 0; mi < 2; ++mi)
                #pragma unroll
                for (int ni = 0; ni < 14; ++ni)
                    #pragma unroll
                    for (int q = 0; q < 4; ++q)
                        acc[mi][ni][q] = 0.0f;
            r0 = sr0; k0 = sk0; n = sn;
            lc = 0;
        } else {
            ++lc;
        }
    }
}

// ---------------- launch -----------------------------------------------------
extern "C" void kernel_launch(void* const* d_in, const int* in_sizes, int n_in,
                              void* d_out, int out_size)
{
    const float* x    = (const float*)d_in[0];
    const float* wgt  = (const float*)d_in[1];
    const float* bias = (const float*)d_in[2];
    float* out        = (float*)d_out;

    cudaFuncSetAttribute(conv_mma_kernel,
                         cudaFuncAttributeMaxDynamicSharedMemorySize, SM_DYN);

    {
        dim3 g(NPIX / 32, CIN / 32, NB + 1);
        dim3 b(32, 8);
        prepass_all<<<g, b>>>(x, wgt);
    }

    conv_mma_kernel<<<148, 256, SM_DYN>>>(bias, out);   // persistent: 1 CTA/SM
}

// round 13
// speedup vs baseline: 1.0684x; 1.0684x over previous
#include <cuda_runtime.h>
#include <cstdint>

#define NB    32
#define CIN   256
#define HH    56
#define WW    56
#define KOUT  256
#define NPIX  (HH*WW)        // 3136
#define KDIM  (CIN*9)        // 2304
#define NCHUNK 72            // 8 c-groups x 9 taps (32 k each)
#define NTILES 1792          // 28 r-tiles(2 rows) x 2 k-groups x 32 images

#define MTILE 128
#define NTILE 112            // 2 rows x 56

// smem: A ring 3 x (128 rows x 128B), B ping-pong 2 x (232 rows x 128B halo)
#define A_STAGE 16384
#define B_ROWS  232          // 4 input rows x 58 cols
#define B_STAGE (B_ROWS*128) // 29696
#define B_SLOTS (B_ROWS*8)   // 1856 vec16 slots
#define SM_DYN (3*A_STAGE + 2*B_STAGE + 128)   // 108672/CTA -> 2 CTAs/SM

// ---------------- device scratch -------------------------------------------
__device__ __align__(16) float g_wt[KOUT * KDIM];               // tf32, c-major chunks
__device__ __align__(16) float g_xt[(size_t)NB * NPIX * CIN];   // NHWC tf32
__device__ unsigned int g_tile_ctr;

// ---------------- PTX helpers ----------------------------------------------
__device__ __forceinline__ uint32_t smem_u32(const void* p) {
    uint32_t a;
    asm("{ .reg .u64 t; cvta.to.shared.u64 t, %1; cvt.u32.u64 %0, t; }"
        : "=r"(a) : "l"(p));
    return a;
}
__device__ __forceinline__ float to_tf32(float v) {
    uint32_t r;
    asm("cvt.rna.tf32.f32 %0, %1;" : "=r"(r) : "f"(v));
    return __uint_as_float(r);
}

#define CP16(dst, src, sz) \
    asm volatile("cp.async.cg.shared.global [%0], [%1], 16, %2;" \
                 :: "r"(dst), "l"(src), "r"(sz) : "memory")
#define CP_COMMIT() asm volatile("cp.async.commit_group;" ::: "memory")
#define CP_WAIT1()  asm volatile("cp.async.wait_group 1;" ::: "memory")

#define LDSM4(r, a) \
    asm volatile("ldmatrix.sync.aligned.m8n8.x4.shared.b16 {%0,%1,%2,%3}, [%4];" \
                 : "=r"((r)[0]),"=r"((r)[1]),"=r"((r)[2]),"=r"((r)[3]) : "r"(a))
#define LDSM2(r, a) \
    asm volatile("ldmatrix.sync.aligned.m8n8.x2.shared.b16 {%0,%1}, [%2];" \
                 : "=r"((r)[0]),"=r"((r)[1]) : "r"(a))

#define MMAT(d, a, b) \
    asm volatile("mma.sync.aligned.m16n8k8.row.col.f32.tf32.tf32.f32 " \
                 "{%0,%1,%2,%3}, {%4,%5,%6,%7}, {%8,%9}, {%0,%1,%2,%3};" \
                 : "+f"((d)[0]),"+f"((d)[1]),"+f"((d)[2]),"+f"((d)[3]) \
                 : "r"((a)[0]),"r"((a)[1]),"r"((a)[2]),"r"((a)[3]), \
                   "r"((b)[0]),"r"((b)[1]))

// ---------------- fused prepass ---------------------------------------------
// z < NB: x NCHW fp32 -> NHWC tf32.  z == NB: weights tf32, c-major chunk order:
//   g_wt[k][ ((c/32)*9 + tap)*32 + (c%32) ]
__global__ void prepass_all(const float* __restrict__ x,
                            const float* __restrict__ w) {
    __shared__ float t[32][33];
    const int tx = threadIdx.x, ty = threadIdx.y;   // 32 x 8

    if (blockIdx.z < NB) {
        const int n  = blockIdx.z;
        const int p0 = blockIdx.x * 32;
        const int c0 = blockIdx.y * 32;

        const float* xb = x + ((size_t)n * CIN + c0) * NPIX + p0;
        #pragma unroll
        for (int yy = ty; yy < 32; yy += 8)
            t[yy][tx] = xb[(size_t)yy * NPIX + tx];
        __syncthreads();

        size_t ob = ((size_t)n * NPIX + p0) * CIN + c0;
        #pragma unroll
        for (int yy = ty; yy < 32; yy += 8)
            g_xt[ob + (size_t)yy * CIN + tx] = to_tf32(t[tx][yy]);
    } else {
        const int b = blockIdx.y * gridDim.x + blockIdx.x;   // 0..783
        const int tl = ty * 32 + tx;
        if (b == 0 && tl == 0) g_tile_ctr = 0u;
        for (int i = b * 256 + tl; i < KOUT * KDIM; i += 784 * 256) {
            int k = i / KDIM, r = i % KDIM;
            int c = r / 9, tap = r % 9;
            int o = k * KDIM + (((c >> 5) * 9 + tap) << 5) + (c & 31);
            g_wt[o] = to_tf32(w[i]);
        }
    }
}

// ---------------- main kernel: persistent, halo-B, 2 CTAs/SM ----------------
__global__ __launch_bounds__(256, 2)
void conv_mma_kernel(const float* __restrict__ bias, float* __restrict__ out)
{
    extern __shared__ __align__(16) char dsm_raw[];
    __shared__ unsigned s_tile;

    const int tid = threadIdx.x;
    const int wid = tid >> 5;
    const int L   = tid & 31;
    const int wm  = wid & 3;             // M quarter
    const int wn  = wid >> 2;            // output row within 2-row tile
    const int kso = (wid & 3) ^ ((wid >> 2) << 1);   // per-warp ks rotation

    uint32_t raw = smem_u32(dsm_raw);
    uint32_t sm  = (raw + 127u) & ~127u;
    uint32_t aB[3] = { sm, sm + A_STAGE, sm + 2 * A_STAGE };
    uint32_t bB[2] = { sm + 3 * A_STAGE, sm + 3 * A_STAGE + B_STAGE };

    // ---- per-lane ldmatrix constants ----
    const int arowL = ((L >> 3) & 1) * 8 + (L & 7);
    const int akg   = L >> 4;
    const int bLane = ((L >> 4) & 1) * 8 + (L & 7);  // x4 pair-load lane row
    const int bkg   = (L >> 3) & 1;
    const int bsLane = 48 + (L & 7);                 // LDSM2 leftover (ni=6)
    const int bskg   = (L >> 3) & 1;

    // ---- staging lambdas (addresses recomputed; tiny state) ----
    auto stageA = [&](int k0t, int chunkCol, uint32_t buf) {
        #pragma unroll
        for (int s = 0; s < 4; ++s) {
            const int slot = tid + s * 256;
            const int p = slot >> 3, v = slot & 7;
            const float* src = g_wt + (size_t)(k0t + p) * KDIM
                                    + (chunkCol << 5) + (v << 2);
            uint32_t bo = (uint32_t)(p << 7) + (v << 4);
            bo ^= (bo >> 3) & 0x70;
            CP16(buf + bo, src, 16u);
        }
    };
    auto stageB = [&](int tn, int tr0, int cgc, int slice, uint32_t buf) {
        const int slot = slice * 256 + tid;
        if (slot < B_SLOTS) {
            const int ri = slot >> 3, v = slot & 7;
            const int inRow = ri / 58;
            const int inCol = ri - inRow * 58;
            const int r = tr0 - 1 + inRow;
            const int w = inCol - 1;
            const bool ok = ((unsigned)r < HH) & ((unsigned)w < WW);
            const int pix = ok ? (r * WW + w) : 0;
            const float* src = g_xt + ((size_t)tn * NPIX + pix) * CIN
                                    + (cgc << 5) + (v << 2);
            uint32_t bo = (uint32_t)(ri << 7) + (v << 4);
            bo ^= (bo >> 3) & 0x70;
            CP16(buf + bo, src, ok ? 16u : 0u);
        }
    };

    float acc[2][7][4];
    #pragma unroll
    for (int mi = 0; mi < 2; ++mi)
        #pragma unroll
        for (int ni = 0; ni < 7; ++ni)
            #pragma unroll
            for (int q = 0; q < 4; ++q)
                acc[mi][ni][q] = 0.0f;

    // ---- acquire first tile ----
    if (tid == 0) s_tile = atomicAdd(&g_tile_ctr, 1u);
    __syncthreads();
    if ((int)s_tile >= NTILES) return;
    int n, r0, k0;
    {
        const int t = (int)s_tile;
        n = t / 56;
        const int rem = t - n * 56;
        k0 = (rem & 1) << 7;
        r0 = (rem >> 1) << 1;
    }
    // prologue: full B halo for c-group 0, A chunks 0 and 1
    #pragma unroll
    for (int t = 0; t < 8; ++t) stageB(n, r0, 0, t, bB[0]);
    stageA(k0, 0, aB[0]); CP_COMMIT();
    stageA(k0, 1, aB[1]); CP_COMMIT();

    int nn = 0, nr0 = 0, nk0 = 0;
    bool vN = false;
    int lc = 0, tap = 0, cg = 0, rd = 0;

    // ---- persistent main loop ----
    while (true) {
        CP_WAIT1();
        __syncthreads();

        if (lc == 61 && tid == 0) s_tile = atomicAdd(&g_tile_ctr, 1u);
        if (lc == 62) {
            const unsigned tt = s_tile;
            vN = (tt < NTILES);
            if (vN) {
                nn = tt / 56;
                const int rem = (int)tt - nn * 56;
                nk0 = (rem & 1) << 7;
                nr0 = (rem >> 1) << 1;
            }
        }

        // ---- stage A for chunk lc+2 ----
        {
            int wrA = rd + 2; if (wrA >= 3) wrA -= 3;
            const int ca = lc + 2;
            if (ca < NCHUNK)      stageA(k0,  ca,          aB[wrA]);
            else if (vN)          stageA(nk0, ca - NCHUNK, aB[wrA]);
        }
        // ---- stage one B halo slice for the next c-group ----
        if (tap < 8) {
            if (cg < 7)      stageB(n,  r0,  cg + 1, tap, bB[(cg + 1) & 1]);
            else if (vN)     stageB(nn, nr0, 0,      tap, bB[0]);
        }
        CP_COMMIT();

        // ---- compute chunk lc (c-group cg, tap) ----
        {
            const uint32_t sA = aB[rd], sB = bB[cg & 1];
            const int kh = tap / 3 - 1;
            const int kw = tap - (tap / 3) * 3 - 1;
            const int Cw = (wn + 1 + kh) * 58 + 1 + kw;   // halo row base
            const int riP = Cw + bLane;                   // x4 pair lane row
            const int riS = Cw + bsLane;                  // LDSM2 lane row

            #pragma unroll
            for (int kk = 0; kk < 4; ++kk) {
                const int ks = (kk + kso) & 3;
                uint32_t bt[7][2];
                #pragma unroll
                for (int pi = 0; pi < 3; ++pi) {
                    const int ri = riP + pi * 16;
                    const int c16 = (ks * 2 + bkg) ^ (ri & 7);
                    LDSM4(&bt[pi * 2][0], sB + (uint32_t)(ri << 7) + (c16 << 4));
                }
                {
                    const int c16 = (ks * 2 + bskg) ^ (riS & 7);
                    LDSM2(bt[6], sB + (uint32_t)(riS << 7) + (c16 << 4));
                }
                uint32_t at[2][4];
                #pragma unroll
                for (int mi = 0; mi < 2; ++mi) {
                    const int row = wm * 32 + mi * 16 + arowL;
                    const int c16 = (ks * 2 + akg) ^ (row & 7);
                    LDSM4(at[mi], sA + (uint32_t)(row << 7) + (c16 << 4));
                }
                #pragma unroll
                for (int mi = 0; mi < 2; ++mi)
                    #pragma unroll
                    for (int ni = 0; ni < 7; ++ni)
                        MMAT(acc[mi][ni], at[mi], bt[ni]);
            }
        }

        rd = (rd == 2) ? 0 : rd + 1;

        if (lc == NCHUNK - 1) {
            // ---- epilogue (hides next tile's refill) ----
            const int gID = L >> 2;
            const int tig = L & 3;
            const int r   = r0 + wn;
            #pragma unroll
            for (int mi = 0; mi < 2; ++mi) {
                const int kbase = k0 + wm * 32 + mi * 16 + gID;
                const float b0 = bias[kbase];
                const float b1 = bias[kbase + 8];
                float* o0 = out + (((size_t)n * KOUT + kbase)     * HH + r) * WW;
                float* o1 = out + (((size_t)n * KOUT + kbase + 8) * HH + r) * WW;
                #pragma unroll
                for (int ni = 0; ni < 7; ++ni) {
                    const int c = ni * 8 + tig * 2;
                    float2 v0 = make_float2(acc[mi][ni][0] + b0, acc[mi][ni][1] + b0);
                    float2 v1 = make_float2(acc[mi][ni][2] + b1, acc[mi][ni][3] + b1);
                    *reinterpret_cast<float2*>(o0 + c) = v0;
                    *reinterpret_cast<float2*>(o1 + c) = v1;
                }
            }
            if (!vN) break;
            #pragma unroll
            for (int mi = 0; mi < 2; ++mi)
                #pragma unroll
                for (int ni = 0; ni < 7; ++ni)
                    #pragma unroll
                    for (int q = 0; q < 4; ++q)
                        acc[mi][ni][q] = 0.0f;
            n = nn; r0 = nr0; k0 = nk0;
            vN = false;
            lc = 0; tap = 0; cg = 0;
        } else {
            ++lc;
            if (++tap == 9) { tap = 0; ++cg; }
        }
    }
}

// ---------------- launch -----------------------------------------------------
extern "C" void kernel_launch(void* const* d_in, const int* in_sizes, int n_in,
                              void* d_out, int out_size)
{
    const float* x    = (const float*)d_in[0];
    const float* wgt  = (const float*)d_in[1];
    const float* bias = (const float*)d_in[2];
    float* out        = (float*)d_out;

    cudaFuncSetAttribute(conv_mma_kernel,
                         cudaFuncAttributeMaxDynamicSharedMemorySize, SM_DYN);

    {
        dim3 g(NPIX / 32, CIN / 32, NB + 1);
        dim3 b(32, 8);
        prepass_all<<<g, b>>>(x, wgt);
    }

    conv_mma_kernel<<<296, 256, SM_DYN>>>(bias, out);   // persistent: 2 CTAs/SM
}

// round 14
// speedup vs baseline: 1.1622x; 1.0878x over previous
#include <cuda_runtime.h>
#include <cstdint>

#define NB    32
#define CIN   256
#define HH    56
#define WW    56
#define KOUT  256
#define NPIX  (HH*WW)        // 3136
#define KDIM  (CIN*9)        // 2304
#define NCHUNK 72            // 8 c-groups x 9 taps (32 k each)
#define NTILES 1792          // 28 r-tiles(2 rows) x 2 k-groups x 32 images

// smem: B halo ping-pong only: 2 x (232 rows x 128B)
#define B_ROWS  232          // 4 input rows x 58 cols
#define B_STAGE (B_ROWS*128) // 29696
#define B_SLOTS (B_ROWS*8)   // 1856 vec16 slots
#define SM_DYN (2*B_STAGE + 256)   // ~59.6KB/CTA -> 2 CTAs/SM

// ---------------- device scratch -------------------------------------------
// A in fragment order: [k0g][chunk][wm][mi][ks][lane] x 4 tf32 (16B per lane)
#define WA_FLOATS (2*NCHUNK*4*2*4*32*4)   // 589824 floats = 2.36MB
__device__ __align__(16) float g_wa[WA_FLOATS];
__device__ __align__(16) float g_xt[(size_t)NB * NPIX * CIN];   // NHWC tf32
__device__ unsigned int g_tile_ctr;

// ---------------- PTX helpers ----------------------------------------------
__device__ __forceinline__ uint32_t smem_u32(const void* p) {
    uint32_t a;
    asm("{ .reg .u64 t; cvta.to.shared.u64 t, %1; cvt.u32.u64 %0, t; }"
        : "=r"(a) : "l"(p));
    return a;
}
__device__ __forceinline__ float to_tf32(float v) {
    uint32_t r;
    asm("cvt.rna.tf32.f32 %0, %1;" : "=r"(r) : "f"(v));
    return __uint_as_float(r);
}

#define CP16(dst, src, sz) \
    asm volatile("cp.async.cg.shared.global [%0], [%1], 16, %2;" \
                 :: "r"(dst), "l"(src), "r"(sz) : "memory")
#define CP_COMMIT() asm volatile("cp.async.commit_group;" ::: "memory")
#define CP_WAIT0()  asm volatile("cp.async.wait_group 0;" ::: "memory")

#define LDSM4(r, a) \
    asm volatile("ldmatrix.sync.aligned.m8n8.x4.shared.b16 {%0,%1,%2,%3}, [%4];" \
                 : "=r"((r)[0]),"=r"((r)[1]),"=r"((r)[2]),"=r"((r)[3]) : "r"(a))
#define LDSM2(r, a) \
    asm volatile("ldmatrix.sync.aligned.m8n8.x2.shared.b16 {%0,%1}, [%2];" \
                 : "=r"((r)[0]),"=r"((r)[1]) : "r"(a))

#define MMAT(d, a, b) \
    asm volatile("mma.sync.aligned.m16n8k8.row.col.f32.tf32.tf32.f32 " \
                 "{%0,%1,%2,%3}, {%4,%5,%6,%7}, {%8,%9}, {%0,%1,%2,%3};" \
                 : "+f"((d)[0]),"+f"((d)[1]),"+f"((d)[2]),"+f"((d)[3]) \
                 : "r"((a).x),"r"((a).y),"r"((a).z),"r"((a).w), \
                   "r"((b)[0]),"r"((b)[1]))

// ---------------- fused prepass ---------------------------------------------
// z < NB: x NCHW fp32 -> NHWC tf32.
// z == NB: weights -> fragment-ordered g_wa (mapping matches the MMA A fragment:
//   reg0=(r, k) reg1=(r+8, k) reg2=(r, k+4) reg3=(r+8, k+4), r=L/4, k=8ks+L%4).
__global__ void prepass_all(const float* __restrict__ x,
                            const float* __restrict__ w) {
    __shared__ float t[32][33];
    const int tx = threadIdx.x, ty = threadIdx.y;   // 32 x 8

    if (blockIdx.z < NB) {
        const int n  = blockIdx.z;
        const int p0 = blockIdx.x * 32;
        const int c0 = blockIdx.y * 32;

        const float* xb = x + ((size_t)n * CIN + c0) * NPIX + p0;
        #pragma unroll
        for (int yy = ty; yy < 32; yy += 8)
            t[yy][tx] = xb[(size_t)yy * NPIX + tx];
        __syncthreads();

        size_t ob = ((size_t)n * NPIX + p0) * CIN + c0;
        #pragma unroll
        for (int yy = ty; yy < 32; yy += 8)
            g_xt[ob + (size_t)yy * CIN + tx] = to_tf32(t[tx][yy]);
    } else {
        const int b = blockIdx.y * gridDim.x + blockIdx.x;   // 0..783
        const int tl = ty * 32 + tx;
        const int idx = b * 256 + tl;                        // lane-slot id
        if (idx == 0) g_tile_ctr = 0u;
        if (idx < WA_FLOATS / 4) {
            const int L  = idx & 31;
            int r = idx >> 5;
            const int ks = r & 3;  r >>= 2;
            const int mi = r & 1;  r >>= 1;
            const int wm = r & 3;  r >>= 2;
            const int ch  = r % NCHUNK;
            const int k0g = r / NCHUNK;
            const int cg = ch / 9, tap = ch - (ch / 9) * 9;
            const int row0 = k0g * 128 + wm * 32 + mi * 16 + (L >> 2);
            const int kc   = cg * 32 + ks * 8 + (L & 3);
            float4 o;
            o.x = to_tf32(w[(size_t)(row0      * CIN + kc    ) * 9 + tap]);
            o.y = to_tf32(w[(size_t)((row0 + 8)* CIN + kc    ) * 9 + tap]);
            o.z = to_tf32(w[(size_t)(row0      * CIN + kc + 4) * 9 + tap]);
            o.w = to_tf32(w[(size_t)((row0 + 8)* CIN + kc + 4) * 9 + tap]);
            reinterpret_cast<float4*>(g_wa)[idx] = o;
        }
    }
}

// ---------------- main kernel: persistent, A-LDG, halo-B, 8 barriers/tile ---
__global__ __launch_bounds__(256, 2)
void conv_mma_kernel(const float* __restrict__ bias, float* __restrict__ out)
{
    extern __shared__ __align__(16) char dsm_raw[];
    __shared__ unsigned s_tile;

    const int tid = threadIdx.x;
    const int wid = tid >> 5;
    const int L   = tid & 31;
    const int wm  = wid & 3;             // M quarter
    const int wn  = wid >> 2;            // output row within 2-row tile

    uint32_t raw = smem_u32(dsm_raw);
    uint32_t sm  = (raw + 127u) & ~127u;
    uint32_t bB[2] = { sm, sm + B_STAGE };

    // ---- per-lane B ldmatrix constants (unchanged from proven R13) ----
    const int bLane  = ((L >> 4) & 1) * 8 + (L & 7);
    const int bkg    = (L >> 3) & 1;
    const int bsLane = 48 + (L & 7);
    const int bskg   = (L >> 3) & 1;

    const uint4* __restrict__ aP = reinterpret_cast<const uint4*>(g_wa);

    // ---- B halo staging (stateless, as R13) ----
    auto stageB = [&](int tn, int tr0, int cgc, int slice, uint32_t buf) {
        const int slot = slice * 256 + tid;
        if (slot < B_SLOTS) {
            const int ri = slot >> 3, v = slot & 7;
            const int inRow = ri / 58;
            const int inCol = ri - inRow * 58;
            const int r = tr0 - 1 + inRow;
            const int w = inCol - 1;
            const bool ok = ((unsigned)r < HH) & ((unsigned)w < WW);
            const int pix = ok ? (r * WW + w) : 0;
            const float* src = g_xt + ((size_t)tn * NPIX + pix) * CIN
                                    + (cgc << 5) + (v << 2);
            uint32_t bo = (uint32_t)(ri << 7) + (v << 4);
            bo ^= (bo >> 3) & 0x70;
            CP16(buf + bo, src, ok ? 16u : 0u);
        }
    };

    float acc[2][7][4];
    #pragma unroll
    for (int mi = 0; mi < 2; ++mi)
        #pragma unroll
        for (int ni = 0; ni < 7; ++ni)
            #pragma unroll
            for (int q = 0; q < 4; ++q)
                acc[mi][ni][q] = 0.0f;

    // ---- acquire first tile ----
    if (tid == 0) s_tile = atomicAdd(&g_tile_ctr, 1u);
    __syncthreads();
    if ((int)s_tile >= NTILES) return;
    int n, r0, k0g;
    {
        const int t = (int)s_tile;
        n = t / 56;
        const int rem = t - n * 56;
        k0g = rem & 1;
        r0 = (rem >> 1) << 1;
    }
    // prologue: full B halo for c-group 0
    #pragma unroll
    for (int t = 0; t < 8; ++t) stageB(n, r0, 0, t, bB[0]);
    CP_COMMIT();

    int nn = 0, nr0 = 0, nk0g = 0;
    bool vN = false;
    int lc = 0, tap = 0, cg = 0;

    // ---- persistent main loop: barrier only at c-group boundaries ----
    while (true) {
        if (tap == 0) {                  // boundary: halo complete + buffer free
            CP_WAIT0();
            __syncthreads();
            if (lc == 63) {              // s_tile written at lc 61; barrier ordered it
                const unsigned tt = s_tile;
                vN = (tt < NTILES);
                if (vN) {
                    nn = tt / 56;
                    const int rem = (int)tt - nn * 56;
                    nk0g = rem & 1;
                    nr0 = (rem >> 1) << 1;
                }
            }
        }
        if (lc == 61 && tid == 0) s_tile = atomicAdd(&g_tile_ctr, 1u);

        // stage one B halo slice for the next c-group / next tile
        if (tap < 8) {
            if (cg < 7)  { stageB(n,  r0,  cg + 1, tap, bB[(cg + 1) & 1]); CP_COMMIT(); }
            else if (vN) { stageB(nn, nr0, 0,      tap, bB[0]);            CP_COMMIT(); }
        }

        // ---- compute chunk lc: A via direct LDG, B via halo LDSM ----
        {
            const uint32_t sB = bB[cg & 1];
            const int kh = tap / 3 - 1;
            const int kw = tap - (tap / 3) * 3 - 1;
            const int Cw = (wn + 1 + kh) * 58 + 1 + kw;
            const int riP = Cw + bLane;
            const int riS = Cw + bsLane;

            // A fragments for the whole chunk: 8 coalesced LDG.128
            const uint4* aC = aP + (size_t)(((k0g * NCHUNK + lc) * 4 + wm) * 2) * 128 + L;
            uint4 aR[2][4];
            #pragma unroll
            for (int mi = 0; mi < 2; ++mi)
                #pragma unroll
                for (int ks = 0; ks < 4; ++ks)
                    aR[mi][ks] = aC[mi * 128 + ks * 32];

            #pragma unroll
            for (int ks = 0; ks < 4; ++ks) {
                uint32_t bt[7][2];
                #pragma unroll
                for (int pi = 0; pi < 3; ++pi) {
                    const int ri = riP + pi * 16;
                    const int c16 = (ks * 2 + bkg) ^ (ri & 7);
                    LDSM4(&bt[pi * 2][0], sB + (uint32_t)(ri << 7) + (c16 << 4));
                }
                {
                    const int c16 = (ks * 2 + bskg) ^ (riS & 7);
                    LDSM2(bt[6], sB + (uint32_t)(riS << 7) + (c16 << 4));
                }
                #pragma unroll
                for (int ni = 0; ni < 7; ++ni) {
                    MMAT(acc[0][ni], aR[0][ks], bt[ni]);
                    MMAT(acc[1][ni], aR[1][ks], bt[ni]);
                }
            }
        }

        if (lc == NCHUNK - 1) {
            // ---- epilogue (no barrier needed; regs only) ----
            const int gID = L >> 2;
            const int tig = L & 3;
            const int r   = r0 + wn;
            #pragma unroll
            for (int mi = 0; mi < 2; ++mi) {
                const int kbase = k0g * 128 + wm * 32 + mi * 16 + gID;
                const float b0 = bias[kbase];
                const float b1 = bias[kbase + 8];
                float* o0 = out + (((size_t)n * KOUT + kbase)     * HH + r) * WW;
                float* o1 = out + (((size_t)n * KOUT + kbase + 8) * HH + r) * WW;
                #pragma unroll
                for (int ni = 0; ni < 7; ++ni) {
                    const int c = ni * 8 + tig * 2;
                    float2 v0 = make_float2(acc[mi][ni][0] + b0, acc[mi][ni][1] + b0);
                    float2 v1 = make_float2(acc[mi][ni][2] + b1, acc[mi][ni][3] + b1);
                    *reinterpret_cast<float2*>(o0 + c) = v0;
                    *reinterpret_cast<float2*>(o1 + c) = v1;
                }
            }
            if (!vN) break;
            #pragma unroll
            for (int mi = 0; mi < 2; ++mi)
                #pragma unroll
                for (int ni = 0; ni < 7; ++ni)
                    #pragma unroll
                    for (int q = 0; q < 4; ++q)
                        acc[mi][ni][q] = 0.0f;
            n = nn; r0 = nr0; k0g = nk0g;
            vN = false;
            lc = 0; tap = 0; cg = 0;
        } else {
            ++lc;
            if (++tap == 9) { tap = 0; ++cg; }
        }
    }
}

// ---------------- launch -----------------------------------------------------
extern "C" void kernel_launch(void* const* d_in, const int* in_sizes, int n_in,
                              void* d_out, int out_size)
{
    const float* x    = (const float*)d_in[0];
    const float* wgt  = (const float*)d_in[1];
    const float* bias = (const float*)d_in[2];
    float* out        = (float*)d_out;

    cudaFuncSetAttribute(conv_mma_kernel,
                         cudaFuncAttributeMaxDynamicSharedMemorySize, SM_DYN);

    {
        dim3 g(NPIX / 32, CIN / 32, NB + 1);   // z=NB: g_wa fill + ctr reset
        dim3 b(32, 8);
        prepass_all<<<g, b>>>(x, wgt);
    }

    conv_mma_kernel<<<296, 256, SM_DYN>>>(bias, out);   // persistent: 2 CTAs/SM
}